// round 3
// baseline (speedup 1.0000x reference)
#include <cuda_runtime.h>

// ---------------------------------------------------------------------------
// SSIM loss, fused single pass, single kernel.
// Tile: 64 (x) x 64 (y) outputs per block, 512 threads.
// Stage 0: load raw img1/img2 tile (5-px zero-padded halo) into smem.
// Stage A: horizontal 11-tap blur of 5 moment fields (a, b, a^2, b^2, ab)
//          into smem H; 8-column register runs, float4 smem I/O.
//          592 jobs over 512 threads (7.8% slot waste).
// Stage B: vertical 11-tap blur + ssim epilogue, 8-row register runs.
// Reduce:  warp shuffle -> block -> atomicAdd(double); last block (counter)
//          writes 1 - mean and resets accumulators (graph-replay safe).
// ---------------------------------------------------------------------------

#define NTHREADS 512
#define TX 64
#define TY 64
#define RROWS 74          // TY + 10
#define RCOLS 74          // TX + 10
#define RSTRIDE 76        // raw row stride (floats), multiple of 4 for LDS.128
#define HSTRIDE 68        // H row stride (floats), multiple of 4
#define IMG 1024
#define NBLOCKS (16 * 16 * 32)

#define SMEM_FLOATS (2 * RROWS * RSTRIDE + 5 * RROWS * HSTRIDE + 16)
#define SMEM_BYTES (SMEM_FLOATS * 4)

static __device__ __forceinline__ float Wt(int t) {
    // Gaussian, WIN=11, SIGMA=1.5, normalized; compile-time constants so
    // ptxas emits FFMA-imm (rt_SMSP=1, 2x tput vs 3-reg FFMA).
    constexpr float w[6] = {0.00102838f, 0.00759875f, 0.03600077f,
                            0.10936069f, 0.21300553f, 0.26601172f};
    return (t < 6) ? w[t] : w[10 - t];
}

__device__ double g_acc = 0.0;
__device__ unsigned g_count = 0u;

__global__ __launch_bounds__(NTHREADS, 1)
void ssim_main(const float* __restrict__ img1, const float* __restrict__ img2,
               float* __restrict__ out) {
    extern __shared__ float smem[];
    float* r1 = smem;                                  // [RROWS][RSTRIDE]
    float* r2 = smem + RROWS * RSTRIDE;                // [RROWS][RSTRIDE]
    float* H  = smem + 2 * RROWS * RSTRIDE;            // [5][RROWS][HSTRIDE]
    float* wsum = H + 5 * RROWS * HSTRIDE;             // [16]

    const float C1f = 0.0004f;   // (0.01*2)^2
    const float C2f = 0.0036f;   // (0.03*2)^2

    const int tid = threadIdx.x;
    const int tx0 = blockIdx.x * TX;
    const int ty0 = blockIdx.y * TY;
    const size_t base = (size_t)blockIdx.z * (size_t)(IMG * IMG);

    // -------- Stage 0: raw tile load (zero-pad outside image) --------------
    for (int idx = tid; idx < RROWS * RCOLS; idx += NTHREADS) {
        const int r = idx / RCOLS;
        const int c = idx - r * RCOLS;
        const int gy = ty0 + r - 5;
        const int gx = tx0 + c - 5;
        float a = 0.f, b = 0.f;
        if ((unsigned)gy < (unsigned)IMG && (unsigned)gx < (unsigned)IMG) {
            const size_t o = base + (size_t)gy * IMG + (size_t)gx;
            a = __ldg(img1 + o);
            b = __ldg(img2 + o);
        }
        r1[r * RSTRIDE + c] = a;
        r2[r * RSTRIDE + c] = b;
    }
    __syncthreads();

    // -------- Stage A: horizontal blur of 5 fields into H ------------------
    // 74 rows x 8 column-groups of 8 = 592 jobs over 512 threads.
    for (int j = tid; j < RROWS * 8; j += NTHREADS) {
        const int r  = j >> 3;
        const int c0 = (j & 7) * 8;
        const float4* p1 = reinterpret_cast<const float4*>(r1 + r * RSTRIDE + c0);
        const float4* p2 = reinterpret_cast<const float4*>(r2 + r * RSTRIDE + c0);
        float in1[20], in2[20];
        #pragma unroll
        for (int q = 0; q < 5; q++) {
            const float4 v1 = p1[q];
            const float4 v2 = p2[q];
            in1[4 * q + 0] = v1.x; in1[4 * q + 1] = v1.y;
            in1[4 * q + 2] = v1.z; in1[4 * q + 3] = v1.w;
            in2[4 * q + 0] = v2.x; in2[4 * q + 1] = v2.y;
            in2[4 * q + 2] = v2.z; in2[4 * q + 3] = v2.w;
        }

        float acc[5][8];
        #pragma unroll
        for (int f = 0; f < 5; f++)
            #pragma unroll
            for (int i = 0; i < 8; i++) acc[f][i] = 0.f;

        #pragma unroll
        for (int k = 0; k < 18; k++) {
            const float a = in1[k];
            const float b = in2[k];
            const float aa = a * a;
            const float bb = b * b;
            const float ab = a * b;
            #pragma unroll
            for (int jj = 0; jj < 8; jj++) {
                const int t = k - jj;
                if (t >= 0 && t <= 10) {
                    const float w = Wt(t);
                    acc[0][jj] += w * a;
                    acc[1][jj] += w * b;
                    acc[2][jj] += w * aa;
                    acc[3][jj] += w * bb;
                    acc[4][jj] += w * ab;
                }
            }
        }
        #pragma unroll
        for (int f = 0; f < 5; f++) {
            float* hp = H + (f * RROWS + r) * HSTRIDE + c0;
            *reinterpret_cast<float4*>(hp) =
                make_float4(acc[f][0], acc[f][1], acc[f][2], acc[f][3]);
            *reinterpret_cast<float4*>(hp + 4) =
                make_float4(acc[f][4], acc[f][5], acc[f][6], acc[f][7]);
        }
    }
    __syncthreads();

    // -------- Stage B: vertical blur + ssim, 8 rows per thread -------------
    float lsum = 0.f;
    {
        const int c  = tid & (TX - 1);          // output column 0..63
        const int g8 = (tid >> 6) * 8;          // first output row (8 groups)
        float v[5][8];
        #pragma unroll
        for (int f = 0; f < 5; f++)
            #pragma unroll
            for (int i = 0; i < 8; i++) v[f][i] = 0.f;

        #pragma unroll
        for (int k = 0; k < 18; k++) {
            float h[5];
            #pragma unroll
            for (int f = 0; f < 5; f++)
                h[f] = H[(f * RROWS + g8 + k) * HSTRIDE + c];
            #pragma unroll
            for (int jj = 0; jj < 8; jj++) {
                const int t = k - jj;
                if (t >= 0 && t <= 10) {
                    const float w = Wt(t);
                    #pragma unroll
                    for (int f = 0; f < 5; f++) v[f][jj] += w * h[f];
                }
            }
        }

        #pragma unroll
        for (int jj = 0; jj < 8; jj++) {
            const float mu1 = v[0][jj];
            const float mu2 = v[1][jj];
            const float mu12 = mu1 * mu2;
            const float mu1s = mu1 * mu1;
            const float mu2s = mu2 * mu2;
            const float s1  = v[2][jj] - mu1s;
            const float s2  = v[3][jj] - mu2s;
            const float s12 = v[4][jj] - mu12;
            const float num = (2.f * mu12 + C1f) * (2.f * s12 + C2f);
            const float den = (mu1s + mu2s + C1f) * (s1 + s2 + C2f);
            lsum += __fdividef(num, den);
        }
    }

    // -------- Reduction ----------------------------------------------------
    #pragma unroll
    for (int o = 16; o > 0; o >>= 1)
        lsum += __shfl_xor_sync(0xffffffffu, lsum, o);
    if ((tid & 31) == 0) wsum[tid >> 5] = lsum;
    __syncthreads();
    if (tid == 0) {
        float bs = 0.f;
        #pragma unroll
        for (int w = 0; w < 16; w++) bs += wsum[w];
        atomicAdd(&g_acc, (double)bs);
        __threadfence();
        const unsigned old = atomicAdd(&g_count, 1u);
        if (old == NBLOCKS - 1) {
            // Last block: all adds are visible (fence + atomic counter).
            const double s = *((volatile double*)&g_acc);
            out[0] = (float)(1.0 - s * (1.0 / 33554432.0));  // 32*1024*1024
            // Reset for the next graph replay (stream-ordered, safe).
            *((volatile double*)&g_acc) = 0.0;
            __threadfence();
            atomicExch(&g_count, 0u);
        }
    }
}

extern "C" void kernel_launch(void* const* d_in, const int* in_sizes, int n_in,
                              void* d_out, int out_size) {
    (void)in_sizes; (void)n_in; (void)out_size;
    const float* img1 = (const float*)d_in[0];
    const float* img2 = (const float*)d_in[1];
    float* out = (float*)d_out;

    static int smem_set = 0;
    if (!smem_set) {
        cudaFuncSetAttribute(ssim_main,
                             cudaFuncAttributeMaxDynamicSharedMemorySize,
                             SMEM_BYTES);
        smem_set = 1;
    }

    dim3 grid(IMG / TX, IMG / TY, 32);   // 16 x 16 x 32 = 8192 blocks
    ssim_main<<<grid, NTHREADS, SMEM_BYTES>>>(img1, img2, out);
}

// round 4
// speedup vs baseline: 2.4058x; 2.4058x over previous
#include <cuda_runtime.h>

// ---------------------------------------------------------------------------
// SSIM loss, fused single pass, single kernel, occupancy-optimized.
// Tile: 64 (x) x 16 (y) outputs per block, 256 threads, 4 blocks/SM target.
// Stage 0: load raw img1/img2 tile (5-px zero-padded halo) into smem.
// Stage A: horizontal 11-tap blur of 5 moment fields (a, b, a^2, b^2, ab)
//          into smem H; 8-column register runs, chunked float4 loads so
//          live registers stay <= 64.  26 rows x 8 groups = 208 jobs (1 pass).
// Stage B: vertical 11-tap blur + ssim epilogue, 4-row runs; 64x4 groups =
//          256 jobs, exactly one per thread (zero imbalance).
// Reduce:  warp shuffle -> block -> atomicAdd(double); last block (counter)
//          writes 1 - mean and resets accumulators (graph-replay safe).
// ---------------------------------------------------------------------------

#define NTHREADS 256
#define TX 64
#define TY 16
#define RROWS 26          // TY + 10
#define RCOLS 74          // TX + 10
#define RSTRIDE 76        // raw row stride (floats), multiple of 4
#define HSTRIDE 68        // H row stride (floats), multiple of 4
#define IMG 1024
#define NBLOCKS (16 * 64 * 32)

#define SMEM_FLOATS (2 * RROWS * RSTRIDE + 5 * RROWS * HSTRIDE + 8)
#define SMEM_BYTES (SMEM_FLOATS * 4)   // 51,200 B -> 4 blocks/SM

static __device__ __forceinline__ float Wt(int t) {
    // Gaussian, WIN=11, SIGMA=1.5, normalized; compile-time constants so
    // ptxas emits FFMA-imm (rt_SMSP=1, 2x tput vs 3-reg FFMA).
    constexpr float w[6] = {0.00102838f, 0.00759875f, 0.03600077f,
                            0.10936069f, 0.21300553f, 0.26601172f};
    return (t < 6) ? w[t] : w[10 - t];
}

__device__ double g_acc = 0.0;
__device__ unsigned g_count = 0u;

__global__ __launch_bounds__(NTHREADS, 4)
void ssim_main(const float* __restrict__ img1, const float* __restrict__ img2,
               float* __restrict__ out) {
    extern __shared__ float smem[];
    float* r1 = smem;                                  // [RROWS][RSTRIDE]
    float* r2 = smem + RROWS * RSTRIDE;                // [RROWS][RSTRIDE]
    float* H  = smem + 2 * RROWS * RSTRIDE;            // [5][RROWS][HSTRIDE]
    float* wsum = H + 5 * RROWS * HSTRIDE;             // [8]

    const float C1f = 0.0004f;   // (0.01*2)^2
    const float C2f = 0.0036f;   // (0.03*2)^2

    const int tid = threadIdx.x;
    const int tx0 = blockIdx.x * TX;
    const int ty0 = blockIdx.y * TY;
    const size_t base = (size_t)blockIdx.z * (size_t)(IMG * IMG);

    // -------- Stage 0: raw tile load (zero-pad outside image) --------------
    #pragma unroll
    for (int idx = tid; idx < RROWS * RCOLS; idx += NTHREADS) {
        const int r = idx / RCOLS;
        const int c = idx - r * RCOLS;
        const int gy = ty0 + r - 5;
        const int gx = tx0 + c - 5;
        float a = 0.f, b = 0.f;
        if ((unsigned)gy < (unsigned)IMG && (unsigned)gx < (unsigned)IMG) {
            const size_t o = base + (size_t)gy * IMG + (size_t)gx;
            a = __ldg(img1 + o);
            b = __ldg(img2 + o);
        }
        r1[r * RSTRIDE + c] = a;
        r2[r * RSTRIDE + c] = b;
    }
    __syncthreads();

    // -------- Stage A: horizontal blur of 5 fields into H ------------------
    // 26 rows x 8 column-groups of 8 = 208 jobs; threads 208..255 idle.
    if (tid < RROWS * 8) {
        const int r  = tid >> 3;
        const int c0 = (tid & 7) * 8;
        const float4* p1 = reinterpret_cast<const float4*>(r1 + r * RSTRIDE + c0);
        const float4* p2 = reinterpret_cast<const float4*>(r2 + r * RSTRIDE + c0);

        float acc[5][8];
        #pragma unroll
        for (int f = 0; f < 5; f++)
            #pragma unroll
            for (int i = 0; i < 8; i++) acc[f][i] = 0.f;

        // Chunked: load one float4 pair, consume its taps, keep regs low.
        #pragma unroll
        for (int q = 0; q < 5; q++) {
            const float4 v1 = p1[q];
            const float4 v2 = p2[q];
            const float a4[4] = {v1.x, v1.y, v1.z, v1.w};
            const float b4[4] = {v2.x, v2.y, v2.z, v2.w};
            #pragma unroll
            for (int i = 0; i < 4; i++) {
                const int k = 4 * q + i;
                if (k < 18) {
                    const float a = a4[i];
                    const float b = b4[i];
                    const float aa = a * a;
                    const float bb = b * b;
                    const float ab = a * b;
                    #pragma unroll
                    for (int jj = 0; jj < 8; jj++) {
                        const int t = k - jj;
                        if (t >= 0 && t <= 10) {
                            const float w = Wt(t);
                            acc[0][jj] += w * a;
                            acc[1][jj] += w * b;
                            acc[2][jj] += w * aa;
                            acc[3][jj] += w * bb;
                            acc[4][jj] += w * ab;
                        }
                    }
                }
            }
        }
        #pragma unroll
        for (int f = 0; f < 5; f++) {
            float* hp = H + (f * RROWS + r) * HSTRIDE + c0;
            *reinterpret_cast<float4*>(hp) =
                make_float4(acc[f][0], acc[f][1], acc[f][2], acc[f][3]);
            *reinterpret_cast<float4*>(hp + 4) =
                make_float4(acc[f][4], acc[f][5], acc[f][6], acc[f][7]);
        }
    }
    __syncthreads();

    // -------- Stage B: vertical blur + ssim, 4 rows per thread -------------
    float lsum = 0.f;
    {
        const int c  = tid & (TX - 1);          // output column 0..63
        const int g4 = (tid >> 6) * 4;          // first output row (4 groups)
        float v[5][4];
        #pragma unroll
        for (int f = 0; f < 5; f++)
            #pragma unroll
            for (int i = 0; i < 4; i++) v[f][i] = 0.f;

        #pragma unroll
        for (int k = 0; k < 14; k++) {
            float h[5];
            #pragma unroll
            for (int f = 0; f < 5; f++)
                h[f] = H[(f * RROWS + g4 + k) * HSTRIDE + c];
            #pragma unroll
            for (int jj = 0; jj < 4; jj++) {
                const int t = k - jj;
                if (t >= 0 && t <= 10) {
                    const float w = Wt(t);
                    #pragma unroll
                    for (int f = 0; f < 5; f++) v[f][jj] += w * h[f];
                }
            }
        }

        #pragma unroll
        for (int jj = 0; jj < 4; jj++) {
            const float mu1 = v[0][jj];
            const float mu2 = v[1][jj];
            const float mu12 = mu1 * mu2;
            const float mu1s = mu1 * mu1;
            const float mu2s = mu2 * mu2;
            const float s1  = v[2][jj] - mu1s;
            const float s2  = v[3][jj] - mu2s;
            const float s12 = v[4][jj] - mu12;
            const float num = (2.f * mu12 + C1f) * (2.f * s12 + C2f);
            const float den = (mu1s + mu2s + C1f) * (s1 + s2 + C2f);
            lsum += __fdividef(num, den);
        }
    }

    // -------- Reduction ----------------------------------------------------
    #pragma unroll
    for (int o = 16; o > 0; o >>= 1)
        lsum += __shfl_xor_sync(0xffffffffu, lsum, o);
    if ((tid & 31) == 0) wsum[tid >> 5] = lsum;
    __syncthreads();
    if (tid == 0) {
        float bs = 0.f;
        #pragma unroll
        for (int w = 0; w < 8; w++) bs += wsum[w];
        atomicAdd(&g_acc, (double)bs);
        __threadfence();
        const unsigned old = atomicAdd(&g_count, 1u);
        if (old == NBLOCKS - 1) {
            // Last block: all adds visible (fence + atomic counter).
            const double s = *((volatile double*)&g_acc);
            out[0] = (float)(1.0 - s * (1.0 / 33554432.0));  // 32*1024*1024
            // Reset for next graph replay (stream-ordered, safe).
            *((volatile double*)&g_acc) = 0.0;
            __threadfence();
            atomicExch(&g_count, 0u);
        }
    }
}

extern "C" void kernel_launch(void* const* d_in, const int* in_sizes, int n_in,
                              void* d_out, int out_size) {
    (void)in_sizes; (void)n_in; (void)out_size;
    const float* img1 = (const float*)d_in[0];
    const float* img2 = (const float*)d_in[1];
    float* out = (float*)d_out;

    static int smem_set = 0;
    if (!smem_set) {
        cudaFuncSetAttribute(ssim_main,
                             cudaFuncAttributeMaxDynamicSharedMemorySize,
                             SMEM_BYTES);
        smem_set = 1;
    }

    dim3 grid(IMG / TX, IMG / TY, 32);   // 16 x 64 x 32 = 32768 blocks
    ssim_main<<<grid, NTHREADS, SMEM_BYTES>>>(img1, img2, out);
}